// round 16
// baseline (speedup 1.0000x reference)
#include <cuda_runtime.h>
#include <cuda_fp16.h>
#include <math.h>
#include <stdint.h>

#define BB 16
#define NN 256
#define DD 128
#define HH 8
#define HDIM 16
#define BN (BB*NN)          // 4096
#define EPSF 1e-8f
#define PI_F 3.14159265358979323846f
#define TWO_PI_F 6.28318530717958647692f
#define INV_TWO_PI_F 0.15915494309189533577f
#define NTILE 16
#define NTP 136             // upper-triangle tile pairs 16*17/2

#define ASTR 72             // layer0 activation row stride (halves)
#define BSTR 72             // B1/B2 row stride (halves)
#define B3STR 24            // B3 row stride (halves)

// ---- k_pair dynamic SMEM layout (bytes) ----
#define SM_AH   0                      // 128*72*2 = 18432
#define SM_AL   18432                  // 18432
#define SM_B1H  36864                  // 64*72*2 = 9216
#define SM_B1L  46080                  // 9216
#define SM_B2H  55296                  // 9216
#define SM_B2L  64512                  // 9216
#define SM_B3H  73728                  // 64*24*2 = 3072
#define SM_B3L  76800                  // 3072
#define SM_SCR  79872                  // 4 warps * 288 floats * 4 = 4608
#define SM_W0   84480                  // 1024
#define SM_SB0  85504                  // 256
#define SM_SB1  85760                  // 256
#define SM_SB2  86016                  // 256
#define SM_SB3  86272                  // 64
#define SM_TOT  86336

// ---- k_attn dynamic SMEM layout ----
#define AT_KS   0                      // 256*20*4 = 20480
#define AT_VS   20480                  // 20480
#define AT_PS   40960                  // 16*256*4 = 16384
#define AT_TOT  57344

// ---------------- scratch ----------------
__device__ float g_part[7*BN];
__device__ float g_bias[BB*HH*NN*NN];
__device__ float g_q[BN*DD];
__device__ float g_k[BN*DD];
__device__ float g_v[BN*DD];
__device__ float g_ao[BN*DD];
// pre-split fp16 weights (zero-init; pads stay 0)
__device__ __align__(16) __half g_w1h[64*BSTR];
__device__ __align__(16) __half g_w1l[64*BSTR];
__device__ __align__(16) __half g_w2h[64*BSTR];
__device__ __align__(16) __half g_w2l[64*BSTR];
__device__ __align__(16) __half g_w3h[64*B3STR];
__device__ __align__(16) __half g_w3l[64*B3STR];

// ---------------- helpers ----------------
__device__ __forceinline__ uint32_t smem_u32(const void* p) {
    uint32_t a;
    asm("{ .reg .u64 t; cvta.to.shared.u64 t, %1; cvt.u32.u64 %0, t; }" : "=r"(a) : "l"(p));
    return a;
}
__device__ __forceinline__ void split_h(float a, __half& hi, __half& lo) {
    hi = __float2half_rn(a);
    lo = __float2half_rn(a - __half2float(hi));
}
// fast tanh-based GELU via MUFU.TANH
__device__ __forceinline__ float gelu_t(float x) {
    const float c = 0.7978845608028654f;   // sqrt(2/pi)
    float u = c * fmaf(0.044715f * x, x * x, x);
    float t;
    asm("tanh.approx.f32 %0, %1;" : "=f"(t) : "f"(u));
    return 0.5f * x * (1.0f + t);
}
// pack 8 floats into hi uint4 + lo uint4
__device__ __forceinline__ void pack8(const float* v, uint4& ph, uint4& pl) {
    uint32_t* phu = (uint32_t*)&ph;
    uint32_t* plu = (uint32_t*)&pl;
    #pragma unroll
    for (int q = 0; q < 4; q++) {
        __half2 hh = __floats2half2_rn(v[2*q+0], v[2*q+1]);
        float2 hf = __half22float2(hh);
        __half2 ll = __floats2half2_rn(v[2*q+0] - hf.x, v[2*q+1] - hf.y);
        phu[q] = *(uint32_t*)&hh;
        plu[q] = *(uint32_t*)&ll;
    }
}
// pack 2 floats into hi u32 + lo u32
__device__ __forceinline__ void pack2(float a, float b, uint32_t& ph, uint32_t& pl) {
    __half2 hh = __floats2half2_rn(a, b);
    float2 hf = __half22float2(hh);
    __half2 ll = __floats2half2_rn(a - hf.x, b - hf.y);
    ph = *(uint32_t*)&hh;
    pl = *(uint32_t*)&ll;
}

// mma.m16n8k16 row.col f32 += f16*f16
__device__ __forceinline__ void mma16816(float* c, const uint32_t* a, const uint32_t* b) {
    asm volatile("mma.sync.aligned.m16n8k16.row.col.f32.f16.f16.f32 "
        "{%0,%1,%2,%3}, {%4,%5,%6,%7}, {%8,%9}, {%0,%1,%2,%3};"
        : "+f"(c[0]), "+f"(c[1]), "+f"(c[2]), "+f"(c[3])
        : "r"(a[0]), "r"(a[1]), "r"(a[2]), "r"(a[3]), "r"(b[0]), "r"(b[1]));
}
__device__ __forceinline__ void ldsm_x4(uint32_t* r, uint32_t addr) {
    asm volatile("ldmatrix.sync.aligned.m8n8.x4.shared.b16 {%0,%1,%2,%3}, [%4];"
        : "=r"(r[0]), "=r"(r[1]), "=r"(r[2]), "=r"(r[3]) : "r"(addr));
}
__device__ __forceinline__ void ldsm_x2t(uint32_t* r, uint32_t addr) {
    asm volatile("ldmatrix.sync.aligned.m8n8.x2.trans.shared.b16 {%0,%1}, [%2];"
        : "=r"(r[0]), "=r"(r[1]) : "r"(addr));
}

// ---------------- kernel 0: pre-split the MLP weights ----------------
__global__ void k_wsplit(const float* __restrict__ w1, const float* __restrict__ w2,
                         const float* __restrict__ w3) {
    int t = blockIdx.x * 256 + threadIdx.x;
    if (t < 4096) {
        int k = t >> 6, n = t & 63;
        __half h, l;
        split_h(w1[t], h, l);
        g_w1h[k*BSTR + n] = h; g_w1l[k*BSTR + n] = l;
        split_h(w2[t], h, l);
        g_w2h[k*BSTR + n] = h; g_w2l[k*BSTR + n] = l;
    }
    if (t < 512) {
        int k = t >> 3, n = t & 7;
        __half h, l;
        split_h(w3[k*8 + n], h, l);
        g_w3h[k*B3STR + n] = h; g_w3l[k*B3STR + n] = l;
    }
}

// ---------------- kernel 1: per-particle features ----------------
__global__ void k_part(const float* __restrict__ x_pf) {
    int idx = blockIdx.x * blockDim.x + threadIdx.x;
    if (idx >= BN) return;
    int b = idx >> 8;
    int n = idx & 255;
    const float* base = x_pf + b * 4 * NN + n;
    float px = base[0];
    float py = base[NN];
    float pz = base[2*NN];
    float e  = base[3*NN];
    float pt  = sqrtf(fmaxf(px*px + py*py, EPSF));
    float rap = 0.5f * log1pf(2.0f * pz / fmaxf(e - pz, 1e-20f));
    float phi = atan2f(py, px);
    g_part[0*BN + idx] = px;
    g_part[1*BN + idx] = py;
    g_part[2*BN + idx] = pz;
    g_part[3*BN + idx] = e;
    g_part[4*BN + idx] = pt;
    g_part[5*BN + idx] = rap;
    g_part[6*BN + idx] = phi;
}

// ---------------- kernel 2: pair MLP, register-resident PTX mma ----------------
// Block = 128 threads = 128 pairs. 4 warps, each owns a 32-row M-slab (2 m16 tiles).
// Both m16 tiles' A fragments live in registers; each B fragment is ldsm'd ONCE
// per layer and feeds both tiles' mmas.
__global__ __launch_bounds__(128) void k_pair(
    const float* __restrict__ w0, const float* __restrict__ b0,
    const float* __restrict__ b1, const float* __restrict__ b2,
    const float* __restrict__ b3)
{
    extern __shared__ __align__(16) unsigned char sm[];
    __half* sAh = (__half*)(sm + SM_AH);
    __half* sAl = (__half*)(sm + SM_AL);
    float* sw0 = (float*)(sm + SM_W0);
    float* sb0 = (float*)(sm + SM_SB0);
    float* sb1 = (float*)(sm + SM_SB1);
    float* sb2 = (float*)(sm + SM_SB2);
    float* sb3 = (float*)(sm + SM_SB3);

    int tid = threadIdx.x;
    int warp = tid >> 5;
    int lane = tid & 31;
    uint32_t smem_base = smem_u32(sm);

    // ---- copy pre-split weights (vector copies) ----
    {
        const uint4* s1h = (const uint4*)g_w1h;
        const uint4* s1l = (const uint4*)g_w1l;
        const uint4* s2h = (const uint4*)g_w2h;
        const uint4* s2l = (const uint4*)g_w2l;
        uint4* d1h = (uint4*)(sm + SM_B1H);
        uint4* d1l = (uint4*)(sm + SM_B1L);
        uint4* d2h = (uint4*)(sm + SM_B2H);
        uint4* d2l = (uint4*)(sm + SM_B2L);
        for (int t = tid; t < 576; t += 128) {
            d1h[t] = s1h[t]; d1l[t] = s1l[t];
            d2h[t] = s2h[t]; d2l[t] = s2l[t];
        }
        const uint4* s3h = (const uint4*)g_w3h;
        const uint4* s3l = (const uint4*)g_w3l;
        uint4* d3h = (uint4*)(sm + SM_B3H);
        uint4* d3l = (uint4*)(sm + SM_B3L);
        for (int t = tid; t < 192; t += 128) { d3h[t] = s3h[t]; d3l[t] = s3l[t]; }
    }
    for (int t = tid; t < 256; t += 128) sw0[t] = w0[t];
    if (tid < 64) { sb0[tid] = b0[tid]; sb1[tid] = b1[tid]; sb2[tid] = b2[tid]; }
    if (tid < 8)  sb3[tid] = b3[tid];

    // ---- tile decode ----
    int bid = blockIdx.x;
    int b   = bid / (NTP * 2);
    int rem = bid - b * (NTP * 2);
    int tp  = rem >> 1;
    int jh  = rem & 1;
    int ti = 0;
    while (tp >= NTILE - ti) { tp -= NTILE - ti; ti++; }
    int tj = ti + tp;

    int il = tid >> 3;                  // 0..15
    int jl = tid & 7;                   // 0..7
    int i  = ti * 16 + il;
    int jbase = tj * 16 + jh * 8;
    int j  = jbase + jl;
    int bi = (b << 8) + i;
    int bj = (b << 8) + j;

    // ---- pairwise features ----
    float pxi = g_part[0*BN+bi], pxj = g_part[0*BN+bj];
    float pyi = g_part[1*BN+bi], pyj = g_part[1*BN+bj];
    float pzi = g_part[2*BN+bi], pzj = g_part[2*BN+bj];
    float ei  = g_part[3*BN+bi], ej  = g_part[3*BN+bj];
    float pti = g_part[4*BN+bi], ptj = g_part[4*BN+bj];
    float rpi = g_part[5*BN+bi], rpj = g_part[5*BN+bj];
    float phi_i = g_part[6*BN+bi], phi_j = g_part[6*BN+bj];

    float drap = rpi - rpj;
    float dw = phi_i - phi_j + PI_F;
    dw -= floorf(dw * INV_TWO_PI_F) * TWO_PI_F;
    float dphi = dw - PI_F;
    float delta = sqrtf(drap*drap + dphi*dphi);
    float lndelta = __logf(fmaxf(delta, EPSF));
    float ptmin = fminf(pti, ptj);
    float lnkt = __logf(fmaxf(ptmin * delta, EPSF));
    float lnz  = __logf(fmaxf(__fdividef(ptmin, fmaxf(pti + ptj, EPSF)), EPSF));
    float es = ei + ej, xs = pxi + pxj, ys = pyi + pyj, zs = pzi + pzj;
    float lnm2 = __logf(fmaxf(es*es - xs*xs - ys*ys - zs*zs, EPSF));
    float f0 = lnkt, f1 = lnz, f2 = lndelta, f3 = lnm2;

    __syncthreads();   // weights ready

    // ---- layer 0 (4->64) per-thread fp32 -> gelu -> split fp16 row tid ----
    {
        float act[64];
        #pragma unroll
        for (int c = 0; c < 64; c += 4) {
            float4 a = *(const float4*)&sb0[c];
            float4 w;
            w = *(const float4*)&sw0[0*64 + c];
            a.x = fmaf(f0,w.x,a.x); a.y = fmaf(f0,w.y,a.y); a.z = fmaf(f0,w.z,a.z); a.w = fmaf(f0,w.w,a.w);
            w = *(const float4*)&sw0[1*64 + c];
            a.x = fmaf(f1,w.x,a.x); a.y = fmaf(f1,w.y,a.y); a.z = fmaf(f1,w.z,a.z); a.w = fmaf(f1,w.w,a.w);
            w = *(const float4*)&sw0[2*64 + c];
            a.x = fmaf(f2,w.x,a.x); a.y = fmaf(f2,w.y,a.y); a.z = fmaf(f2,w.z,a.z); a.w = fmaf(f2,w.w,a.w);
            w = *(const float4*)&sw0[3*64 + c];
            a.x = fmaf(f3,w.x,a.x); a.y = fmaf(f3,w.y,a.y); a.z = fmaf(f3,w.z,a.z); a.w = fmaf(f3,w.w,a.w);
            act[c+0] = gelu_t(a.x); act[c+1] = gelu_t(a.y);
            act[c+2] = gelu_t(a.z); act[c+3] = gelu_t(a.w);
        }
        #pragma unroll
        for (int c = 0; c < 64; c += 8) {
            uint4 ph, pl;
            pack8(&act[c], ph, pl);
            *(uint4*)&sAh[tid*ASTR + c] = ph;
            *(uint4*)&sAl[tid*ASTR + c] = pl;
        }
    }
    __syncwarp();      // warp slab complete (warps only read their own rows)

    float* scr = (float*)(sm + SM_SCR) + warp * 288;   // [32 rows][9]

    // ---- A fragments for both m16 tiles from layer0 SMEM ----
    uint32_t Ah[2][4][4], Al[2][4][4];
    #pragma unroll
    for (int mt = 0; mt < 2; mt++) {
        uint32_t row = (uint32_t)(warp*32 + mt*16 + (lane & 15));
        uint32_t col = (uint32_t)((lane >> 4) << 3);
        uint32_t off = (row*ASTR + col) * 2;
        #pragma unroll
        for (int kt = 0; kt < 4; kt++) {
            ldsm_x4(Ah[mt][kt], smem_base + SM_AH + off + kt*32);
            ldsm_x4(Al[mt][kt], smem_base + SM_AL + off + kt*32);
        }
    }

    // ---- layers 1 & 2: B fragment loaded once, feeds both mt tiles ----
    #pragma unroll 1
    for (int layer = 0; layer < 2; layer++) {
        uint32_t boff = (layer == 0) ? SM_B1H : SM_B2H;
        const float* bias = (layer == 0) ? sb1 : sb2;

        float C[2][8][4];
        #pragma unroll
        for (int mt = 0; mt < 2; mt++)
            #pragma unroll
            for (int nt = 0; nt < 8; nt++)
                #pragma unroll
                for (int q = 0; q < 4; q++) C[mt][nt][q] = 0.0f;

        uint32_t brow_off = ((uint32_t)(lane & 15) * BSTR) * 2;
        #pragma unroll
        for (int kt = 0; kt < 4; kt++) {
            uint32_t kaddr = smem_base + boff + kt*16*BSTR*2 + brow_off;
            #pragma unroll
            for (int nt = 0; nt < 8; nt++) {
                uint32_t bh[2], bl[2];
                ldsm_x2t(bh, kaddr + nt*16);
                ldsm_x2t(bl, kaddr + nt*16 + 9216);
                #pragma unroll
                for (int mt = 0; mt < 2; mt++) {
                    mma16816(C[mt][nt], Ah[mt][kt], bh);
                    mma16816(C[mt][nt], Ah[mt][kt], bl);
                    mma16816(C[mt][nt], Al[mt][kt], bh);
                }
            }
        }

        // bias + gelu + split-pack back into A fragments
        int cb = (lane & 3) * 2;
        #pragma unroll
        for (int mt = 0; mt < 2; mt++) {
            #pragma unroll
            for (int k2 = 0; k2 < 4; k2++) {
                float be0 = bias[(2*k2)*8 + cb],   bo0 = bias[(2*k2)*8 + cb + 1];
                float be1 = bias[(2*k2+1)*8 + cb], bo1 = bias[(2*k2+1)*8 + cb + 1];
                float g0 = gelu_t(C[mt][2*k2][0] + be0);
                float g1 = gelu_t(C[mt][2*k2][1] + bo0);
                float g2 = gelu_t(C[mt][2*k2][2] + be0);
                float g3 = gelu_t(C[mt][2*k2][3] + bo0);
                float g4 = gelu_t(C[mt][2*k2+1][0] + be1);
                float g5 = gelu_t(C[mt][2*k2+1][1] + bo1);
                float g6 = gelu_t(C[mt][2*k2+1][2] + be1);
                float g7 = gelu_t(C[mt][2*k2+1][3] + bo1);
                pack2(g0, g1, Ah[mt][k2][0], Al[mt][k2][0]);
                pack2(g2, g3, Ah[mt][k2][1], Al[mt][k2][1]);
                pack2(g4, g5, Ah[mt][k2][2], Al[mt][k2][2]);
                pack2(g6, g7, Ah[mt][k2][3], Al[mt][k2][3]);
            }
        }
    }

    // ---- layer 3: 64 -> 8 (single n8 tile), B loaded once for both mt ----
    {
        float C3[2][4];
        #pragma unroll
        for (int mt = 0; mt < 2; mt++)
            #pragma unroll
            for (int q = 0; q < 4; q++) C3[mt][q] = 0.0f;
        uint32_t brow_off = ((uint32_t)(lane & 15) * B3STR) * 2;
        #pragma unroll
        for (int kt = 0; kt < 4; kt++) {
            uint32_t kaddr = smem_base + SM_B3H + kt*16*B3STR*2 + brow_off;
            uint32_t bh[2], bl[2];
            ldsm_x2t(bh, kaddr);
            ldsm_x2t(bl, kaddr + 3072);
            #pragma unroll
            for (int mt = 0; mt < 2; mt++) {
                mma16816(C3[mt], Ah[mt][kt], bh);
                mma16816(C3[mt], Ah[mt][kt], bl);
                mma16816(C3[mt], Al[mt][kt], bh);
            }
        }
        int g = lane >> 2;
        int h0 = (lane & 3) * 2;
        #pragma unroll
        for (int mt = 0; mt < 2; mt++) {
            int r0 = mt*16 + g;
            scr[(r0    )*9 + h0    ] = C3[mt][0] + sb3[h0];
            scr[(r0    )*9 + h0 + 1] = C3[mt][1] + sb3[h0+1];
            scr[(r0 + 8)*9 + h0    ] = C3[mt][2] + sb3[h0];
            scr[(r0 + 8)*9 + h0 + 1] = C3[mt][3] + sb3[h0+1];
        }
    }
    __syncwarp();

    // each thread picks up its own pair's 8 outputs
    float outv[8];
    #pragma unroll
    for (int h = 0; h < 8; h++) outv[h] = scr[lane*9 + h];

    // ---- direct write [b,h,i,j] ----
    #pragma unroll
    for (int h = 0; h < 8; h++)
        g_bias[(((b*8 + h)*256 + i))*256 + j] = outv[h];

    // ---- mirror write [b,h,j,i] via staging (reuse B1H region) ----
    __syncthreads();
    float* st = (float*)(sm + SM_B1H);     // [8][8][18] floats = 4608B
    #pragma unroll
    for (int h = 0; h < 8; h++) st[(h*8 + jl)*18 + il] = outv[h];
    __syncthreads();
    for (int t = tid; t < 256; t += 128) {
        int h = t >> 5, r = t & 31, jl2 = r >> 2, iq = r & 3;
        const float* s = &st[(h*8 + jl2)*18 + iq*4];
        float4 v = make_float4(s[0], s[1], s[2], s[3]);
        int jrow = jbase + jl2;
        float* q = g_bias + (((b*8 + h)*256 + jrow))*256 + ti*16 + iq*4;
        *(float4*)q = v;
    }
}

// ---------------- kernel 3: QKV projections (256 thr: 2 halves x 4 rows) ----------------
__global__ __launch_bounds__(256) void k_qkv(
    const float* __restrict__ xf,
    const float* __restrict__ wq, const float* __restrict__ wk, const float* __restrict__ wv,
    const float* __restrict__ bq, const float* __restrict__ bk, const float* __restrict__ bv)
{
    __shared__ float xs[8][128];
    int tid = threadIdx.x;
    int d = tid & 127;
    int half = tid >> 7;
    int r0 = blockIdx.x * 8;
    for (int t = tid; t < 8*128; t += 256) xs[t >> 7][t & 127] = xf[r0*128 + t];
    __syncthreads();

    float aq[4], ak[4], av[4];
    float bqv = bq[d], bkv = bk[d], bvv = bv[d];
    #pragma unroll
    for (int r = 0; r < 4; r++) { aq[r] = bqv; ak[r] = bkv; av[r] = bvv; }

    const float* xr = &xs[half*4][0];
    #pragma unroll 8
    for (int k = 0; k < 128; k++) {
        float wqv = wq[k*128 + d];
        float wkv = wk[k*128 + d];
        float wvv = wv[k*128 + d];
        #pragma unroll
        for (int r = 0; r < 4; r++) {
            float x = xr[r*128 + k];
            aq[r] = fmaf(x, wqv, aq[r]);
            ak[r] = fmaf(x, wkv, ak[r]);
            av[r] = fmaf(x, wvv, av[r]);
        }
    }
    #pragma unroll
    for (int r = 0; r < 4; r++) {
        int row = r0 + half*4 + r;
        g_q[row*128 + d] = aq[r];
        g_k[row*128 + d] = ak[r];
        g_v[row*128 + d] = av[r];
    }
}

// ---------------- kernel 4: attention, 2 rows per warp, 32 rows per block ----------------
__global__ __launch_bounds__(256, 2) void k_attn() {
    extern __shared__ __align__(16) unsigned char smd[];
    float (*ks)[20] = (float(*)[20])(smd + AT_KS);
    float (*vs)[20] = (float(*)[20])(smd + AT_VS);
    float (*ps)[256] = (float(*)[256])(smd + AT_PS);

    int bid = blockIdx.x;          // grid = 16*8*8 = 1024
    int it = bid & 7;              // 32-row tile
    int h  = (bid >> 3) & 7;
    int b  = bid >> 6;

    int tid = threadIdx.x;
    {
        int j = tid;
        const float* kp = g_k + (b*256 + j)*128 + h*16;
        const float* vp = g_v + (b*256 + j)*128 + h*16;
        #pragma unroll
        for (int d = 0; d < 16; d += 4) {
            *(float4*)&ks[j][d] = *(const float4*)&kp[d];
            *(float4*)&vs[j][d] = *(const float4*)&vp[d];
        }
    }
    __syncthreads();

    int w = tid >> 5;
    int lane = tid & 31;

    #pragma unroll 1
    for (int pr = 0; pr < 2; pr++) {
        int i0 = it*32 + w*4 + pr*2;           // rows i0, i0+1

        const float* qp0 = g_q + (b*256 + i0)*128 + h*16;
        float q0[16], q1[16];
        #pragma unroll
        for (int d = 0; d < 16; d++) { q0[d] = qp0[d]; q1[d] = qp0[128 + d]; }

        const float* bp0 = g_bias + ((b*8 + h)*256 + i0)*256;
        float bb0[8], bb1[8];
        #pragma unroll
        for (int jj = 0; jj < 8; jj++) {
            bb0[jj] = bp0[jj*32 + lane];
            bb1[jj] = bp0[256 + jj*32 + lane];
        }

        float s0[8], s1[8];
        float m0 = -1e30f, m1 = -1e30f;
        #pragma unroll
        for (int jj = 0; jj < 8; jj++) {
            int j = jj*32 + lane;
            float4 k0 = *(const float4*)&ks[j][0];
            float4 k1 = *(const float4*)&ks[j][4];
            float4 k2 = *(const float4*)&ks[j][8];
            float4 k3 = *(const float4*)&ks[j][12];
            float e0 = q0[0]*k0.x;
            e0 = fmaf(q0[1],k0.y,e0); e0 = fmaf(q0[2],k0.z,e0); e0 = fmaf(q0[3],k0.w,e0);
            e0 = fmaf(q0[4],k1.x,e0); e0 = fmaf(q0[5],k1.y,e0); e0 = fmaf(q0[6],k1.z,e0); e0 = fmaf(q0[7],k1.w,e0);
            float e1 = q0[8]*k2.x;
            e1 = fmaf(q0[9],k2.y,e1);  e1 = fmaf(q0[10],k2.z,e1); e1 = fmaf(q0[11],k2.w,e1);
            e1 = fmaf(q0[12],k3.x,e1); e1 = fmaf(q0[13],k3.y,e1); e1 = fmaf(q0[14],k3.z,e1); e1 = fmaf(q0[15],k3.w,e1);
            s0[jj] = (e0 + e1) * 0.25f + bb0[jj];
            m0 = fmaxf(m0, s0[jj]);
            float f0 = q1[0]*k0.x;
            f0 = fmaf(q1[1],k0.y,f0); f0 = fmaf(q1[2],k0.z,f0); f0 = fmaf(q1[3],k0.w,f0);
            f0 = fmaf(q1[4],k1.x,f0); f0 = fmaf(q1[5],k1.y,f0); f0 = fmaf(q1[6],k1.z,f0); f0 = fmaf(q1[7],k1.w,f0);
            float f1 = q1[8]*k2.x;
            f1 = fmaf(q1[9],k2.y,f1);  f1 = fmaf(q1[10],k2.z,f1); f1 = fmaf(q1[11],k2.w,f1);
            f1 = fmaf(q1[12],k3.x,f1); f1 = fmaf(q1[13],k3.y,f1); f1 = fmaf(q1[14],k3.z,f1); f1 = fmaf(q1[15],k3.w,f1);
            s1[jj] = (f0 + f1) * 0.25f + bb1[jj];
            m1 = fmaxf(m1, s1[jj]);
        }
        #pragma unroll
        for (int off = 16; off >= 1; off >>= 1) {
            m0 = fmaxf(m0, __shfl_xor_sync(0xffffffffu, m0, off));
            m1 = fmaxf(m1, __shfl_xor_sync(0xffffffffu, m1, off));
        }
        float sum0 = 0.0f, sum1 = 0.0f;
        #pragma unroll
        for (int jj = 0; jj < 8; jj++) {
            s0[jj] = __expf(s0[jj] - m0); sum0 += s0[jj];
            s1[jj] = __expf(s1[jj] - m1); sum1 += s1[jj];
        }
        #pragma unroll
        for (int off = 16; off >= 1; off >>= 1) {
            sum0 += __shfl_xor_sync(0xffffffffu, sum0, off);
            sum1 += __shfl_xor_sync(0xffffffffu, sum1, off);
        }
        float inv0 = __fdividef(1.0f, sum0);
        float inv1 = __fdividef(1.0f, sum1);

        int sl0 = w*2, sl1 = w*2 + 1;
        #pragma unroll
        for (int jj = 0; jj < 8; jj++) {
            ps[sl0][jj*32 + lane] = s0[jj] * inv0;
            ps[sl1][jj*32 + lane] = s1[jj] * inv1;
        }
        __syncwarp();

        {
            int d4 = lane & 3;
            int jp = lane >> 2;
            float4 a0 = make_float4(0.f,0.f,0.f,0.f);
            float4 a1 = make_float4(0.f,0.f,0.f,0.f);
            #pragma unroll 4
            for (int jj = 0; jj < 32; jj++) {
                int j = jj*8 + jp;
                float4 v = *(const float4*)&vs[j][d4*4];
                float p0 = ps[sl0][j];
                float p1 = ps[sl1][j];
                a0.x = fmaf(p0, v.x, a0.x); a0.y = fmaf(p0, v.y, a0.y);
                a0.z = fmaf(p0, v.z, a0.z); a0.w = fmaf(p0, v.w, a0.w);
                a1.x = fmaf(p1, v.x, a1.x); a1.y = fmaf(p1, v.y, a1.y);
                a1.z = fmaf(p1, v.z, a1.z); a1.w = fmaf(p1, v.w, a1.w);
            }
            #pragma unroll
            for (int off = 4; off <= 16; off <<= 1) {
                a0.x += __shfl_xor_sync(0xffffffffu, a0.x, off);
                a0.y += __shfl_xor_sync(0xffffffffu, a0.y, off);
                a0.z += __shfl_xor_sync(0xffffffffu, a0.z, off);
                a0.w += __shfl_xor_sync(0xffffffffu, a0.w, off);
                a1.x += __shfl_xor_sync(0xffffffffu, a1.x, off);
                a1.y += __shfl_xor_sync(0xffffffffu, a1.y, off);
                a1.z += __shfl_xor_sync(0xffffffffu, a1.z, off);
                a1.w += __shfl_xor_sync(0xffffffffu, a1.w, off);
            }
            if (jp == 0) {
                *(float4*)&g_ao[(b*256 + i0)*128 + h*16 + d4*4] = a0;
                *(float4*)&g_ao[(b*256 + i0 + 1)*128 + h*16 + d4*4] = a1;
            }
        }
        __syncwarp();
    }
}

// ---------------- kernel 5: output projection (256 thr: 2 halves x 4 rows) ----------------
__global__ __launch_bounds__(256) void k_outproj(
    const float* __restrict__ wo, const float* __restrict__ bo, float* __restrict__ out)
{
    __shared__ float xs[8][128];
    int tid = threadIdx.x;
    int d = tid & 127;
    int half = tid >> 7;
    int r0 = blockIdx.x * 8;
    for (int t = tid; t < 8*128; t += 256) xs[t >> 7][t & 127] = g_ao[r0*128 + t];
    __syncthreads();

    float acc[4];
    float bv = bo[d];
    #pragma unroll
    for (int r = 0; r < 4; r++) acc[r] = bv;

    const float* xr = &xs[half*4][0];
    #pragma unroll 8
    for (int k = 0; k < 128; k++) {
        float wv = wo[k*128 + d];
        #pragma unroll
        for (int r = 0; r < 4; r++) acc[r] = fmaf(xr[r*128 + k], wv, acc[r]);
    }
    #pragma unroll
    for (int r = 0; r < 4; r++) out[(r0 + half*4 + r)*128 + d] = acc[r];
}

// ---------------- launch ----------------
extern "C" void kernel_launch(void* const* d_in, const int* in_sizes, int n_in,
                              void* d_out, int out_size) {
    (void)in_sizes; (void)n_in; (void)out_size;
    const float* x_pf   = (const float*)d_in[0];
    const float* x_feat = (const float*)d_in[1];
    const float* w0 = (const float*)d_in[2];
    const float* b0 = (const float*)d_in[3];
    const float* w1 = (const float*)d_in[4];
    const float* b1 = (const float*)d_in[5];
    const float* w2 = (const float*)d_in[6];
    const float* b2 = (const float*)d_in[7];
    const float* w3 = (const float*)d_in[8];
    const float* b3 = (const float*)d_in[9];
    const float* wq = (const float*)d_in[10];
    const float* wk = (const float*)d_in[11];
    const float* wv = (const float*)d_in[12];
    const float* wo = (const float*)d_in[13];
    const float* bq = (const float*)d_in[14];
    const float* bk = (const float*)d_in[15];
    const float* bv = (const float*)d_in[16];
    const float* bo = (const float*)d_in[17];

    cudaFuncSetAttribute(k_pair, cudaFuncAttributeMaxDynamicSharedMemorySize, SM_TOT);
    cudaFuncSetAttribute(k_attn, cudaFuncAttributeMaxDynamicSharedMemorySize, AT_TOT);

    k_wsplit<<<16, 256>>>(w1, w2, w3);
    k_part<<<16, 256>>>(x_pf);
    k_pair<<<BB*NTP*2, 128, SM_TOT>>>(w0, b0, b1, b2, b3);
    k_qkv<<<512, 256>>>(x_feat, wq, wk, wv, bq, bk, bv);
    k_attn<<<1024, 256, AT_TOT>>>();
    k_outproj<<<512, 256>>>(wo, bo, (float*)d_out);
}